// round 4
// baseline (speedup 1.0000x reference)
#include <cuda_runtime.h>
#include <math.h>

#define NN   50000
#define E0   800000
#define ETOT 850000
#define F1   256          // heads*HID  (layer-1 concat width)
#define F2   512          // heads*OUT  (layer-2 pre-mean width)

// ---------------- scratch (device globals; no allocations) ----------------
__device__ float    g_h1[(size_t)NN * F1];     // layer1 pre-attn features, later h_relu
__device__ float    g_acc1[(size_t)NN * F1];   // layer1 message accumulator
__device__ float    g_h2[(size_t)NN * F2];     // layer2 pre-attn features
__device__ float    g_acc2[(size_t)NN * F2];   // layer2 message accumulator
__device__ float    g_e[(size_t)ETOT * 4];     // per-edge leaky-relu scores (4 heads)
__device__ float    g_es[NN * 4];              // e_src per node/head
__device__ float    g_ed[NN * 4];              // e_dst per node/head
__device__ unsigned g_m[NN * 4];               // segment max (order-preserving uint encoding)
__device__ float    g_den[NN * 4];             // softmax denominator
__device__ int      g_is64;                    // 1 if edge_index is int64, 0 if int32

// ---------------- helpers ----------------
__device__ __forceinline__ unsigned f2ord(float f) {
    unsigned u = __float_as_uint(f);
    return (u & 0x80000000u) ? ~u : (u | 0x80000000u);
}
__device__ __forceinline__ float ord2f(unsigned u) {
    return (u & 0x80000000u) ? __uint_as_float(u & 0x7fffffffu) : __uint_as_float(~u);
}

// Resolve (src,dst) for edge e, honoring detected index dtype. Edges >= E0 are self loops.
__device__ __forceinline__ void edge_nodes(const void* __restrict__ ei, int e,
                                           int& src, int& dst) {
    if (e >= E0) { src = dst = e - E0; return; }
    if (g_is64) {
        const long long* p = (const long long*)ei;
        src = (int)p[e];
        dst = (int)p[E0 + e];
    } else {
        const int* p = (const int*)ei;
        src = p[e];
        dst = p[E0 + e];
    }
}

// ---------------- dtype detection (head of graph, single block) ----------------
// int64 little-endian with values in [0,50000) -> every odd 32-bit word is 0.
// int32 -> odd words are random node ids; all-zero over 128 samples is impossible.
__global__ void detect_idx_kernel(const int* __restrict__ ei32) {
    if (threadIdx.x == 0) {
        int all0 = 1;
        for (int i = 1; i < 256; i += 2) all0 &= (ei32[i] == 0);
        g_is64 = all0;
    }
}

// ---------------- zero scratch ----------------
__global__ void zero_l1() {
    size_t i  = (size_t)blockIdx.x * blockDim.x + threadIdx.x;
    size_t st = (size_t)gridDim.x * blockDim.x;
    for (size_t j = i; j < (size_t)NN * F1; j += st) g_acc1[j] = 0.f;
    for (size_t j = i; j < (size_t)NN * 4;  j += st) { g_m[j] = 0u; g_den[j] = 0.f; }
}
__global__ void zero_l2() {
    size_t i  = (size_t)blockIdx.x * blockDim.x + threadIdx.x;
    size_t st = (size_t)gridDim.x * blockDim.x;
    for (size_t j = i; j < (size_t)NN * F2; j += st) g_acc2[j] = 0.f;
    for (size_t j = i; j < (size_t)NN * 4;  j += st) { g_m[j] = 0u; g_den[j] = 0.f; }
}

// ---------------- tiled fp32 GEMM: C[n,J] = A[n,K] @ B[K,J] ----------------
// BM=BN=64, BK=16, 256 threads, 4x4 microtile. K%16==0, J%64==0.
__global__ void gemm_kernel(const float* __restrict__ A, const float* __restrict__ B,
                            float* __restrict__ C, int n, int K, int J) {
    __shared__ float As[16][68];
    __shared__ float Bs[16][64];
    int tid = threadIdx.x;
    int tx = tid & 15, ty = tid >> 4;
    int row0 = blockIdx.y * 64;
    int col0 = blockIdx.x * 64;
    float acc[4][4] = {};
    for (int k0 = 0; k0 < K; k0 += 16) {
        {   // A tile: 64x16, one float4/thread, store transposed
            int r  = tid >> 2;
            int kq = tid & 3;
            int grow = row0 + r;
            float4 v = make_float4(0.f, 0.f, 0.f, 0.f);
            if (grow < n)
                v = *reinterpret_cast<const float4*>(A + (size_t)grow * K + k0 + kq * 4);
            As[kq * 4 + 0][r] = v.x;
            As[kq * 4 + 1][r] = v.y;
            As[kq * 4 + 2][r] = v.z;
            As[kq * 4 + 3][r] = v.w;
        }
        {   // B tile: 16x64, one float4/thread
            int kr = tid >> 4;
            int c4 = tid & 15;
            float4 v = *reinterpret_cast<const float4*>(B + (size_t)(k0 + kr) * J + col0 + c4 * 4);
            *reinterpret_cast<float4*>(&Bs[kr][c4 * 4]) = v;
        }
        __syncthreads();
#pragma unroll
        for (int k = 0; k < 16; k++) {
            float a[4], b[4];
#pragma unroll
            for (int i = 0; i < 4; i++) a[i] = As[k][ty * 4 + i];
#pragma unroll
            for (int j = 0; j < 4; j++) b[j] = Bs[k][tx * 4 + j];
#pragma unroll
            for (int i = 0; i < 4; i++)
#pragma unroll
                for (int j = 0; j < 4; j++) acc[i][j] += a[i] * b[j];
        }
        __syncthreads();
    }
#pragma unroll
    for (int i = 0; i < 4; i++) {
        int grow = row0 + ty * 4 + i;
        if (grow < n) {
#pragma unroll
            for (int j = 0; j < 4; j++)
                C[(size_t)grow * J + col0 + tx * 4 + j] = acc[i][j];
        }
    }
}

// ---------------- per-node attention scores: es/ed[n,h] = h[n,h,:]·a ----------------
// warp per node; lanes 8k..8k+7 own head k.
template <int C>  // per-head channels (64 or 128)
__global__ void attn_scores(const float* __restrict__ h, const float* __restrict__ a_src,
                            const float* __restrict__ a_dst, float* __restrict__ es,
                            float* __restrict__ ed) {
    int warp = (blockIdx.x * blockDim.x + threadIdx.x) >> 5;
    int lane = threadIdx.x & 31;
    if (warp >= NN) return;
    const float4* hr  = reinterpret_cast<const float4*>(h + (size_t)warp * 4 * C);
    const float4* as4 = reinterpret_cast<const float4*>(a_src);
    const float4* ad4 = reinterpret_cast<const float4*>(a_dst);
    constexpr int Q = C / 32;  // float4 per lane
    float ss = 0.f, sd = 0.f;
#pragma unroll
    for (int q = 0; q < Q; q++) {
        int idx = lane * Q + q;  // lanes grouped by head
        float4 hv = hr[idx];
        float4 av = as4[idx];
        float4 dv = ad4[idx];
        ss += hv.x * av.x + hv.y * av.y + hv.z * av.z + hv.w * av.w;
        sd += hv.x * dv.x + hv.y * dv.y + hv.z * dv.z + hv.w * dv.w;
    }
#pragma unroll
    for (int off = 4; off >= 1; off >>= 1) {
        ss += __shfl_down_sync(0xffffffffu, ss, off);
        sd += __shfl_down_sync(0xffffffffu, sd, off);
    }
    if ((lane & 7) == 0) {
        int head = lane >> 3;
        es[warp * 4 + head] = ss;
        ed[warp * 4 + head] = sd;
    }
}

// ---------------- pass A: per-edge scores + segment max ----------------
__global__ void edge_max(const void* __restrict__ ei, const float* __restrict__ es,
                         const float* __restrict__ ed, float* __restrict__ ebuf,
                         unsigned* __restrict__ m) {
    int e = blockIdx.x * blockDim.x + threadIdx.x;
    if (e >= ETOT) return;
    int src, dst;
    edge_nodes(ei, e, src, dst);
    float4 a = *reinterpret_cast<const float4*>(es + src * 4);
    float4 b = *reinterpret_cast<const float4*>(ed + dst * 4);
    float v[4] = {a.x + b.x, a.y + b.y, a.z + b.z, a.w + b.w};
#pragma unroll
    for (int h = 0; h < 4; h++) {
        float x = v[h];
        x = x > 0.f ? x : 0.2f * x;     // leaky relu, slope 0.2
        v[h] = x;
        atomicMax(&m[dst * 4 + h], f2ord(x));
    }
    *reinterpret_cast<float4*>(ebuf + (size_t)e * 4) = make_float4(v[0], v[1], v[2], v[3]);
}

// ---------------- pass B: exp, denom, and unnormalized message accumulate ----------------
// warp per edge; coalesced float4 gathers from h[src] and float4 REDs into acc[dst].
template <int C>
__global__ void edge_accum(const void* __restrict__ ei, const float* __restrict__ ebuf,
                           const unsigned* __restrict__ m, const float* __restrict__ h,
                           float* __restrict__ den, float* __restrict__ acc) {
    int e    = (int)((blockIdx.x * blockDim.x + threadIdx.x) >> 5);
    int lane = threadIdx.x & 31;
    if (e >= ETOT) return;
    int src, dst;
    edge_nodes(ei, e, src, dst);
    float4 ev = *reinterpret_cast<const float4*>(ebuf + (size_t)e * 4);
    uint4  mu = *reinterpret_cast<const uint4*>(m + dst * 4);
    float ex[4];
    ex[0] = expf(ev.x - ord2f(mu.x));
    ex[1] = expf(ev.y - ord2f(mu.y));
    ex[2] = expf(ev.z - ord2f(mu.z));
    ex[3] = expf(ev.w - ord2f(mu.w));
    if (lane < 4) atomicAdd(&den[dst * 4 + lane], ex[lane]);
    const float4* hs = reinterpret_cast<const float4*>(h + (size_t)src * 4 * C);
    float4*       ad = reinterpret_cast<float4*>(acc + (size_t)dst * 4 * C);
    constexpr int Q = C / 32;  // total 4*C floats = C float4 per edge
#pragma unroll
    for (int q = 0; q < Q; q++) {
        int idx  = q * 32 + lane;        // coalesced
        int head = idx / (C / 4);        // C/4 float4 per head
        float s  = ex[head];
        float4 v = hs[idx];
        atomicAdd(&ad[idx], make_float4(v.x * s, v.y * s, v.z * s, v.w * s));
    }
}

// ---------------- layer-1 finalize: normalize + bias + relu ----------------
__global__ void finalize1(const float* __restrict__ acc, const float* __restrict__ den,
                          const float* __restrict__ b1, float* __restrict__ out) {
    int i = blockIdx.x * blockDim.x + threadIdx.x;
    if (i >= NN * F1) return;
    int n = i >> 8;          // / 256
    int c = i & 255;
    float d = den[n * 4 + (c >> 6)] + 1e-16f;
    float v = acc[i] / d + b1[c];
    out[i] = v > 0.f ? v : 0.f;
}

// ---------------- layer-2 finalize: normalize + head-mean + bias + layernorm ----------------
__global__ void finalize2_ln(const float* __restrict__ acc, const float* __restrict__ den,
                             const float* __restrict__ b2, const float* __restrict__ gamma,
                             const float* __restrict__ beta, float* __restrict__ out) {
    int n = blockIdx.x;
    int c = threadIdx.x;  // 0..127
    float4 d4 = *reinterpret_cast<const float4*>(den + n * 4);
    size_t base = (size_t)n * F2;
    float s = acc[base + 0 * 128 + c] / (d4.x + 1e-16f)
            + acc[base + 1 * 128 + c] / (d4.y + 1e-16f)
            + acc[base + 2 * 128 + c] / (d4.z + 1e-16f)
            + acc[base + 3 * 128 + c] / (d4.w + 1e-16f);
    float y = s * 0.25f + b2[c];

    __shared__ float red[4];
    float t = y;
#pragma unroll
    for (int off = 16; off >= 1; off >>= 1) t += __shfl_down_sync(0xffffffffu, t, off);
    if ((c & 31) == 0) red[c >> 5] = t;
    __syncthreads();
    float mu = (red[0] + red[1] + red[2] + red[3]) * (1.f / 128.f);
    float dv = y - mu;
    t = dv * dv;
#pragma unroll
    for (int off = 16; off >= 1; off >>= 1) t += __shfl_down_sync(0xffffffffu, t, off);
    __syncthreads();
    if ((c & 31) == 0) red[c >> 5] = t;
    __syncthreads();
    float var = (red[0] + red[1] + red[2] + red[3]) * (1.f / 128.f);
    out[(size_t)n * 128 + c] = dv * rsqrtf(var + 1e-5f) * gamma[c] + beta[c];
}

// ---------------- launch ----------------
extern "C" void kernel_launch(void* const* d_in, const int* in_sizes, int n_in,
                              void* d_out, int out_size) {
    const float* x     = (const float*)d_in[0];
    const void*  ei    = d_in[1];               // int32 or int64, detected on device
    const float* W1    = (const float*)d_in[2];
    const float* as1   = (const float*)d_in[3];
    const float* ad1   = (const float*)d_in[4];
    const float* b1    = (const float*)d_in[5];
    const float* W2    = (const float*)d_in[6];
    const float* as2   = (const float*)d_in[7];
    const float* ad2   = (const float*)d_in[8];
    const float* b2    = (const float*)d_in[9];
    const float* gamma = (const float*)d_in[10];
    const float* beta  = (const float*)d_in[11];
    float*       out   = (float*)d_out;

    float *p_h1, *p_acc1, *p_h2, *p_acc2, *p_e, *p_es, *p_ed, *p_den;
    unsigned* p_m;
    cudaGetSymbolAddress((void**)&p_h1,   g_h1);
    cudaGetSymbolAddress((void**)&p_acc1, g_acc1);
    cudaGetSymbolAddress((void**)&p_h2,   g_h2);
    cudaGetSymbolAddress((void**)&p_acc2, g_acc2);
    cudaGetSymbolAddress((void**)&p_e,    g_e);
    cudaGetSymbolAddress((void**)&p_es,   g_es);
    cudaGetSymbolAddress((void**)&p_ed,   g_ed);
    cudaGetSymbolAddress((void**)&p_m,    g_m);
    cudaGetSymbolAddress((void**)&p_den,  g_den);

    const int TB = 256;
    int rowsBlocks = (NN + 63) / 64;              // 782
    int nodeWarpBlocks = (NN + 7) / 8;            // 6250 (8 warps/block)
    int edgeBlocks = (ETOT + TB - 1) / TB;        // 3321
    int edgeWarpBlocks = (ETOT + 7) / 8;          // 106250

    detect_idx_kernel<<<1, 32>>>((const int*)ei);

    // ---- layer 1 ----
    zero_l1<<<2048, TB>>>();
    gemm_kernel<<<dim3(F1 / 64, rowsBlocks), TB>>>(x, W1, p_h1, NN, 128, F1);
    attn_scores<64><<<nodeWarpBlocks, TB>>>(p_h1, as1, ad1, p_es, p_ed);
    edge_max<<<edgeBlocks, TB>>>(ei, p_es, p_ed, p_e, p_m);
    edge_accum<64><<<edgeWarpBlocks, TB>>>(ei, p_e, p_m, p_h1, p_den, p_acc1);
    finalize1<<<(NN * F1 + TB - 1) / TB, TB>>>(p_acc1, p_den, b1, p_h1);  // h_relu -> g_h1

    // ---- layer 2 ----
    zero_l2<<<2048, TB>>>();
    gemm_kernel<<<dim3(F2 / 64, rowsBlocks), TB>>>(p_h1, W2, p_h2, NN, 256, F2);
    attn_scores<128><<<nodeWarpBlocks, TB>>>(p_h2, as2, ad2, p_es, p_ed);
    edge_max<<<edgeBlocks, TB>>>(ei, p_es, p_ed, p_e, p_m);
    edge_accum<128><<<edgeWarpBlocks, TB>>>(ei, p_e, p_m, p_h2, p_den, p_acc2);
    finalize2_ln<<<NN, 128>>>(p_acc2, p_den, b2, gamma, beta, out);
}

// round 6
// speedup vs baseline: 1.8814x; 1.8814x over previous
#include <cuda_runtime.h>
#include <math.h>

#define NN   50000
#define E0   800000
#define ETOT 850000
#define F1   256          // heads*HID  (layer-1 concat width)
#define F2   512          // heads*OUT  (layer-2 pre-mean width)

// ---------------- scratch (device globals; no allocations) ----------------
__device__ float g_h1[(size_t)NN * F1];    // layer1 pre-attn features
__device__ float g_hr[(size_t)NN * F1];    // layer1 post-attn relu output (GEMM2 input)
__device__ float g_h2[(size_t)NN * F2];    // layer2 pre-attn features
__device__ float g_es[NN * 4];             // e_src per node/head
__device__ float g_ed[NN * 4];             // e_dst per node/head
__device__ int   g_deg[NN];                // in-degree histogram
__device__ int   g_rowptr[NN + 1];         // CSR row offsets (by dst)
__device__ int   g_pos[NN];                // scatter cursors
__device__ int   g_srcs[ETOT];             // CSR column (src) indices
__device__ int   g_is64;                   // 1 if edge_index is int64

// ---------------- dtype helpers ----------------
__device__ __forceinline__ void edge_nodes(const void* __restrict__ ei, int e,
                                           int& src, int& dst) {
    if (e >= E0) { src = dst = e - E0; return; }
    if (g_is64) {
        const long long* p = (const long long*)ei;
        src = (int)p[e];
        dst = (int)p[E0 + e];
    } else {
        const int* p = (const int*)ei;
        src = p[e];
        dst = p[E0 + e];
    }
}

// int64 little-endian node ids < 2^31 -> odd 32-bit words all zero.
__global__ void detect_idx_kernel(const int* __restrict__ ei32) {
    if (threadIdx.x == 0) {
        int all0 = 1;
        for (int i = 1; i < 256; i += 2) all0 &= (ei32[i] == 0);
        g_is64 = all0;
    }
}

// ---------------- CSR build ----------------
__global__ void zero_deg() {
    int i = blockIdx.x * blockDim.x + threadIdx.x;
    if (i < NN) g_deg[i] = 0;
}

__global__ void hist_kernel(const void* __restrict__ ei) {
    int e = blockIdx.x * blockDim.x + threadIdx.x;
    if (e >= ETOT) return;
    int src, dst;
    edge_nodes(ei, e, src, dst);
    atomicAdd(&g_deg[dst], 1);
}

// single block, 1024 threads: chunked exclusive scan of g_deg -> rowptr/pos
__global__ void scan_kernel() {
    __shared__ int part[1024];
    int tid = threadIdx.x;
    const int CH = (NN + 1023) / 1024;   // 49
    int lo = tid * CH;
    int hi = lo + CH; if (hi > NN) hi = NN;
    if (lo > NN) lo = NN;
    int s = 0;
    for (int i = lo; i < hi; i++) s += g_deg[i];
    part[tid] = s;
    __syncthreads();
    for (int off = 1; off < 1024; off <<= 1) {
        int v = part[tid];
        int add = (tid >= off) ? part[tid - off] : 0;
        __syncthreads();
        part[tid] = v + add;
        __syncthreads();
    }
    int run = (tid == 0) ? 0 : part[tid - 1];
    for (int i = lo; i < hi; i++) {
        g_rowptr[i] = run;
        g_pos[i]    = run;
        run += g_deg[i];
    }
    if (tid == 1023) g_rowptr[NN] = part[1023];
}

__global__ void scatter_kernel(const void* __restrict__ ei) {
    int e = blockIdx.x * blockDim.x + threadIdx.x;
    if (e >= ETOT) return;
    int src, dst;
    edge_nodes(ei, e, src, dst);
    int p = atomicAdd(&g_pos[dst], 1);
    g_srcs[p] = src;
}

// ---------------- tf32 tensor-core GEMM: C[n,J] = A[n,K] @ B[K,J] ----------------
// block tile 64(M) x 128(N), K-step 32, 256 threads = 8 warps (2m x 4n), warp 32x32.
__device__ __forceinline__ unsigned f2tf32(float f) {
    unsigned r;
    asm("cvt.rna.tf32.f32 %0, %1;" : "=r"(r) : "f"(f));
    return r;
}
__device__ __forceinline__ void mma_tf32(float* d, const unsigned* a, const unsigned* b) {
    asm volatile(
        "mma.sync.aligned.m16n8k8.row.col.f32.tf32.tf32.f32 "
        "{%0,%1,%2,%3}, {%4,%5,%6,%7}, {%8,%9}, {%0,%1,%2,%3};"
        : "+f"(d[0]), "+f"(d[1]), "+f"(d[2]), "+f"(d[3])
        : "r"(a[0]), "r"(a[1]), "r"(a[2]), "r"(a[3]), "r"(b[0]), "r"(b[1]));
}

__global__ __launch_bounds__(256) void gemm_tf32(const float* __restrict__ A,
                                                 const float* __restrict__ B,
                                                 float* __restrict__ C,
                                                 int n, int K, int J) {
    __shared__ unsigned As[64][36];    // read bank = (4*lr+lc)%32, all 32 distinct
    __shared__ unsigned Bs[32][136];   // 128-wide tile + pad 8; read bank = (8*lc+lr)%32, distinct
    int tid  = threadIdx.x;
    int warp = tid >> 5, lane = tid & 31;
    int wm = (warp & 1) * 32;
    int wn = (warp >> 1) * 32;
    int row0 = blockIdx.y * 64;
    int col0 = blockIdx.x * 128;
    int lr = lane >> 2, lc = lane & 3;

    float acc[2][4][4];
#pragma unroll
    for (int i = 0; i < 2; i++)
#pragma unroll
        for (int j = 0; j < 4; j++)
#pragma unroll
            for (int q = 0; q < 4; q++) acc[i][j][q] = 0.f;

    for (int k0 = 0; k0 < K; k0 += 32) {
        {   // A tile 64x32: thread loads 8 floats (2 float4)
            int ar = tid >> 2;
            int ac = (tid & 3) * 8;
            int grow = row0 + ar;
            float4 v0 = make_float4(0.f, 0.f, 0.f, 0.f), v1 = v0;
            if (grow < n) {
                const float* ap = A + (size_t)grow * K + k0 + ac;
                v0 = *reinterpret_cast<const float4*>(ap);
                v1 = *reinterpret_cast<const float4*>(ap + 4);
            }
            As[ar][ac + 0] = f2tf32(v0.x); As[ar][ac + 1] = f2tf32(v0.y);
            As[ar][ac + 2] = f2tf32(v0.z); As[ar][ac + 3] = f2tf32(v0.w);
            As[ar][ac + 4] = f2tf32(v1.x); As[ar][ac + 5] = f2tf32(v1.y);
            As[ar][ac + 6] = f2tf32(v1.z); As[ar][ac + 7] = f2tf32(v1.w);
        }
        {   // B tile 32x128: thread loads 16 floats (4 float4)
            int br = tid >> 3;
            int bc = (tid & 7) * 16;
            const float* bp = B + (size_t)(k0 + br) * J + col0 + bc;
#pragma unroll
            for (int q = 0; q < 4; q++) {
                float4 v = *reinterpret_cast<const float4*>(bp + q * 4);
                Bs[br][bc + q * 4 + 0] = f2tf32(v.x);
                Bs[br][bc + q * 4 + 1] = f2tf32(v.y);
                Bs[br][bc + q * 4 + 2] = f2tf32(v.z);
                Bs[br][bc + q * 4 + 3] = f2tf32(v.w);
            }
        }
        __syncthreads();
#pragma unroll
        for (int kk = 0; kk < 32; kk += 8) {
            unsigned a[2][4], b[4][2];
#pragma unroll
            for (int mf = 0; mf < 2; mf++) {
                int r = wm + mf * 16 + lr;
                a[mf][0] = As[r][kk + lc];
                a[mf][1] = As[r + 8][kk + lc];
                a[mf][2] = As[r][kk + lc + 4];
                a[mf][3] = As[r + 8][kk + lc + 4];
            }
#pragma unroll
            for (int nf = 0; nf < 4; nf++) {
                int c = wn + nf * 8 + lr;
                b[nf][0] = Bs[kk + lc][c];
                b[nf][1] = Bs[kk + lc + 4][c];
            }
#pragma unroll
            for (int mf = 0; mf < 2; mf++)
#pragma unroll
                for (int nf = 0; nf < 4; nf++)
                    mma_tf32(acc[mf][nf], a[mf], b[nf]);
        }
        __syncthreads();
    }
    // store: c0 (r, c), c1 (r, c+1), c2 (r+8, c), c3 (r+8, c+1)
#pragma unroll
    for (int mf = 0; mf < 2; mf++) {
#pragma unroll
        for (int nf = 0; nf < 4; nf++) {
            int r = row0 + wm + mf * 16 + lr;
            int c = col0 + wn + nf * 8 + 2 * lc;
            if (r < n) {
                C[(size_t)r * J + c]     = acc[mf][nf][0];
                C[(size_t)r * J + c + 1] = acc[mf][nf][1];
            }
            if (r + 8 < n) {
                C[(size_t)(r + 8) * J + c]     = acc[mf][nf][2];
                C[(size_t)(r + 8) * J + c + 1] = acc[mf][nf][3];
            }
        }
    }
}

// ---------------- per-node attention scores: es/ed[n,h] = h[n,h,:]·a ----------------
template <int C>  // per-head channels (64 or 128)
__global__ void attn_scores(const float* __restrict__ h, const float* __restrict__ a_src,
                            const float* __restrict__ a_dst, float* __restrict__ es,
                            float* __restrict__ ed) {
    int warp = (blockIdx.x * blockDim.x + threadIdx.x) >> 5;
    int lane = threadIdx.x & 31;
    if (warp >= NN) return;
    const float4* hr  = reinterpret_cast<const float4*>(h + (size_t)warp * 4 * C);
    const float4* as4 = reinterpret_cast<const float4*>(a_src);
    const float4* ad4 = reinterpret_cast<const float4*>(a_dst);
    constexpr int Q = C / 32;
    float ss = 0.f, sd = 0.f;
#pragma unroll
    for (int q = 0; q < Q; q++) {
        int idx = lane * Q + q;  // lanes grouped by head (head = lane>>3)
        float4 hv = hr[idx];
        float4 av = as4[idx];
        float4 dv = ad4[idx];
        ss += hv.x * av.x + hv.y * av.y + hv.z * av.z + hv.w * av.w;
        sd += hv.x * dv.x + hv.y * dv.y + hv.z * dv.z + hv.w * dv.w;
    }
#pragma unroll
    for (int off = 4; off >= 1; off >>= 1) {
        ss += __shfl_down_sync(0xffffffffu, ss, off);
        sd += __shfl_down_sync(0xffffffffu, sd, off);
    }
    if ((lane & 7) == 0) {
        int head = lane >> 3;
        es[warp * 4 + head] = ss;
        ed[warp * 4 + head] = sd;
    }
}

// ---------------- fused per-node GAT aggregation ----------------
__device__ __forceinline__ float4 leaky4(float4 a, float4 b) {
    float4 v;
    v.x = a.x + b.x; v.x = v.x > 0.f ? v.x : 0.2f * v.x;
    v.y = a.y + b.y; v.y = v.y > 0.f ? v.y : 0.2f * v.y;
    v.z = a.z + b.z; v.z = v.z > 0.f ? v.z : 0.2f * v.z;
    v.w = a.w + b.w; v.w = v.w > 0.f ? v.w : 0.2f * v.w;
    return v;
}
__device__ __forceinline__ float4 max4(float4 a, float4 b) {
    return make_float4(fmaxf(a.x, b.x), fmaxf(a.y, b.y), fmaxf(a.z, b.z), fmaxf(a.w, b.w));
}

#define CHUNK 64

// Layer 1: segmax + softmax + accumulate + bias + relu.  128 threads/block, VEC=2.
__global__ __launch_bounds__(128) void gat_agg1(
    const float* __restrict__ h, const float* __restrict__ es, const float* __restrict__ ed,
    const float* __restrict__ bias, float* __restrict__ out) {
    int n = blockIdx.x;
    int tid = threadIdx.x;
    int lane = tid & 31, wid = tid >> 5;  // wid == head for owned channels
    int r0 = g_rowptr[n], r1 = g_rowptr[n + 1];
    int deg = r1 - r0;
    float4 edv = *reinterpret_cast<const float4*>(ed + n * 4);

    __shared__ float4 s_red[4];
    __shared__ int    s_src[CHUNK];
    __shared__ float4 s_w[CHUNK];

    // phase 1: per-head max
    float4 mx = make_float4(-1e30f, -1e30f, -1e30f, -1e30f);
    for (int i = tid; i < deg; i += 128) {
        int s = g_srcs[r0 + i];
        float4 e = leaky4(*reinterpret_cast<const float4*>(es + s * 4), edv);
        mx = max4(mx, e);
    }
#pragma unroll
    for (int off = 16; off >= 1; off >>= 1) {
        mx.x = fmaxf(mx.x, __shfl_xor_sync(0xffffffffu, mx.x, off));
        mx.y = fmaxf(mx.y, __shfl_xor_sync(0xffffffffu, mx.y, off));
        mx.z = fmaxf(mx.z, __shfl_xor_sync(0xffffffffu, mx.z, off));
        mx.w = fmaxf(mx.w, __shfl_xor_sync(0xffffffffu, mx.w, off));
    }
    if (lane == 0) s_red[wid] = mx;
    __syncthreads();
    mx = max4(max4(s_red[0], s_red[1]), max4(s_red[2], s_red[3]));
    __syncthreads();

    // phase 2: chunked weights + accumulate
    float a0 = 0.f, a1 = 0.f;       // channels tid*2, tid*2+1 (head = wid)
    float4 dpart = make_float4(0.f, 0.f, 0.f, 0.f);
    for (int base = 0; base < deg; base += CHUNK) {
        int cn = deg - base; if (cn > CHUNK) cn = CHUNK;
        if (tid < cn) {
            int s = g_srcs[r0 + base + tid];
            float4 e = leaky4(*reinterpret_cast<const float4*>(es + s * 4), edv);
            float4 w = make_float4(__expf(e.x - mx.x), __expf(e.y - mx.y),
                                   __expf(e.z - mx.z), __expf(e.w - mx.w));
            s_src[tid] = s;
            s_w[tid] = w;
            dpart.x += w.x; dpart.y += w.y; dpart.z += w.z; dpart.w += w.w;
        }
        __syncthreads();
        const float* wf = reinterpret_cast<const float*>(s_w);
        for (int j = 0; j < cn; j++) {
            int s = s_src[j];
            float w = wf[j * 4 + wid];
            float2 hv = *reinterpret_cast<const float2*>(h + (size_t)s * F1 + tid * 2);
            a0 += w * hv.x;
            a1 += w * hv.y;
        }
        __syncthreads();
    }
    // reduce denom
#pragma unroll
    for (int off = 16; off >= 1; off >>= 1) {
        dpart.x += __shfl_xor_sync(0xffffffffu, dpart.x, off);
        dpart.y += __shfl_xor_sync(0xffffffffu, dpart.y, off);
        dpart.z += __shfl_xor_sync(0xffffffffu, dpart.z, off);
        dpart.w += __shfl_xor_sync(0xffffffffu, dpart.w, off);
    }
    if (lane == 0) s_red[wid] = dpart;
    __syncthreads();
    float4 dt = s_red[0];
    dt.x += s_red[1].x + s_red[2].x + s_red[3].x;
    dt.y += s_red[1].y + s_red[2].y + s_red[3].y;
    dt.z += s_red[1].z + s_red[2].z + s_red[3].z;
    dt.w += s_red[1].w + s_red[2].w + s_red[3].w;
    float den = ((const float*)&dt)[wid] + 1e-16f;
    float inv = 1.f / den;
    int c = tid * 2;
    float o0 = a0 * inv + bias[c];
    float o1 = a1 * inv + bias[c + 1];
    o0 = o0 > 0.f ? o0 : 0.f;
    o1 = o1 > 0.f ? o1 : 0.f;
    *reinterpret_cast<float2*>(out + (size_t)n * F1 + c) = make_float2(o0, o1);
}

// Layer 2: segmax + softmax + accumulate + head-mean + bias + LayerNorm. VEC=4.
__global__ __launch_bounds__(128) void gat_agg2(
    const float* __restrict__ h, const float* __restrict__ es, const float* __restrict__ ed,
    const float* __restrict__ bias, const float* __restrict__ gamma,
    const float* __restrict__ beta, float* __restrict__ out) {
    int n = blockIdx.x;
    int tid = threadIdx.x;
    int lane = tid & 31, wid = tid >> 5;  // head = wid for owned channels
    int r0 = g_rowptr[n], r1 = g_rowptr[n + 1];
    int deg = r1 - r0;
    float4 edv = *reinterpret_cast<const float4*>(ed + n * 4);

    __shared__ float4 s_red[4];
    __shared__ int    s_src[CHUNK];
    __shared__ float4 s_w[CHUNK];
    __shared__ float  s_y[F2];
    __shared__ float  s_ln[4];

    float4 mx = make_float4(-1e30f, -1e30f, -1e30f, -1e30f);
    for (int i = tid; i < deg; i += 128) {
        int s = g_srcs[r0 + i];
        float4 e = leaky4(*reinterpret_cast<const float4*>(es + s * 4), edv);
        mx = max4(mx, e);
    }
#pragma unroll
    for (int off = 16; off >= 1; off >>= 1) {
        mx.x = fmaxf(mx.x, __shfl_xor_sync(0xffffffffu, mx.x, off));
        mx.y = fmaxf(mx.y, __shfl_xor_sync(0xffffffffu, mx.y, off));
        mx.z = fmaxf(mx.z, __shfl_xor_sync(0xffffffffu, mx.z, off));
        mx.w = fmaxf(mx.w, __shfl_xor_sync(0xffffffffu, mx.w, off));
    }
    if (lane == 0) s_red[wid] = mx;
    __syncthreads();
    mx = max4(max4(s_red[0], s_red[1]), max4(s_red[2], s_red[3]));
    __syncthreads();

    float a0 = 0.f, a1 = 0.f, a2 = 0.f, a3 = 0.f;  // channels 4*tid..4*tid+3
    float4 dpart = make_float4(0.f, 0.f, 0.f, 0.f);
    for (int base = 0; base < deg; base += CHUNK) {
        int cn = deg - base; if (cn > CHUNK) cn = CHUNK;
        if (tid < cn) {
            int s = g_srcs[r0 + base + tid];
            float4 e = leaky4(*reinterpret_cast<const float4*>(es + s * 4), edv);
            float4 w = make_float4(__expf(e.x - mx.x), __expf(e.y - mx.y),
                                   __expf(e.z - mx.z), __expf(e.w - mx.w));
            s_src[tid] = s;
            s_w[tid] = w;
            dpart.x += w.x; dpart.y += w.y; dpart.z += w.z; dpart.w += w.w;
        }
        __syncthreads();
        const float* wf = reinterpret_cast<const float*>(s_w);
        for (int j = 0; j < cn; j++) {
            int s = s_src[j];
            float w = wf[j * 4 + wid];
            float4 hv = *reinterpret_cast<const float4*>(h + (size_t)s * F2 + tid * 4);
            a0 += w * hv.x;
            a1 += w * hv.y;
            a2 += w * hv.z;
            a3 += w * hv.w;
        }
        __syncthreads();
    }
#pragma unroll
    for (int off = 16; off >= 1; off >>= 1) {
        dpart.x += __shfl_xor_sync(0xffffffffu, dpart.x, off);
        dpart.y += __shfl_xor_sync(0xffffffffu, dpart.y, off);
        dpart.z += __shfl_xor_sync(0xffffffffu, dpart.z, off);
        dpart.w += __shfl_xor_sync(0xffffffffu, dpart.w, off);
    }
    if (lane == 0) s_red[wid] = dpart;
    __syncthreads();
    float4 dt = s_red[0];
    dt.x += s_red[1].x + s_red[2].x + s_red[3].x;
    dt.y += s_red[1].y + s_red[2].y + s_red[3].y;
    dt.z += s_red[1].z + s_red[2].z + s_red[3].z;
    dt.w += s_red[1].w + s_red[2].w + s_red[3].w;
    float inv = 1.f / (((const float*)&dt)[wid] + 1e-16f);
    int l = tid * 4;
    s_y[l + 0] = a0 * inv;
    s_y[l + 1] = a1 * inv;
    s_y[l + 2] = a2 * inv;
    s_y[l + 3] = a3 * inv;
    __syncthreads();

    // head-mean + bias, then LayerNorm over 128 channels
    int c = tid;
    float y = 0.25f * (s_y[c] + s_y[128 + c] + s_y[256 + c] + s_y[384 + c]) + bias[c];
    float t = y;
#pragma unroll
    for (int off = 16; off >= 1; off >>= 1) t += __shfl_xor_sync(0xffffffffu, t, off);
    if (lane == 0) s_ln[wid] = t;
    __syncthreads();
    float mu = (s_ln[0] + s_ln[1] + s_ln[2] + s_ln[3]) * (1.f / 128.f);
    float dv = y - mu;
    t = dv * dv;
#pragma unroll
    for (int off = 16; off >= 1; off >>= 1) t += __shfl_xor_sync(0xffffffffu, t, off);
    __syncthreads();
    if (lane == 0) s_ln[wid] = t;
    __syncthreads();
    float var = (s_ln[0] + s_ln[1] + s_ln[2] + s_ln[3]) * (1.f / 128.f);
    out[(size_t)n * 128 + c] = dv * rsqrtf(var + 1e-5f) * gamma[c] + beta[c];
}

// ---------------- launch ----------------
extern "C" void kernel_launch(void* const* d_in, const int* in_sizes, int n_in,
                              void* d_out, int out_size) {
    const float* x     = (const float*)d_in[0];
    const void*  ei    = d_in[1];               // int32 or int64, detected on device
    const float* W1    = (const float*)d_in[2];
    const float* as1   = (const float*)d_in[3];
    const float* ad1   = (const float*)d_in[4];
    const float* b1    = (const float*)d_in[5];
    const float* W2    = (const float*)d_in[6];
    const float* as2   = (const float*)d_in[7];
    const float* ad2   = (const float*)d_in[8];
    const float* b2    = (const float*)d_in[9];
    const float* gamma = (const float*)d_in[10];
    const float* beta  = (const float*)d_in[11];
    float*       out   = (float*)d_out;

    float *p_h1, *p_hr, *p_h2, *p_es, *p_ed;
    cudaGetSymbolAddress((void**)&p_h1, g_h1);
    cudaGetSymbolAddress((void**)&p_hr, g_hr);
    cudaGetSymbolAddress((void**)&p_h2, g_h2);
    cudaGetSymbolAddress((void**)&p_es, g_es);
    cudaGetSymbolAddress((void**)&p_ed, g_ed);

    const int TB = 256;
    int rowsBlocks = (NN + 63) / 64;            // 782
    int nodeWarpBlocks = (NN + 7) / 8;          // 6250
    int edgeBlocks = (ETOT + TB - 1) / TB;      // 3321

    // ---- CSR build (shared by both layers) ----
    detect_idx_kernel<<<1, 32>>>((const int*)ei);
    zero_deg<<<(NN + TB - 1) / TB, TB>>>();
    hist_kernel<<<edgeBlocks, TB>>>(ei);
    scan_kernel<<<1, 1024>>>();
    scatter_kernel<<<edgeBlocks, TB>>>(ei);

    // ---- layer 1 ----
    gemm_tf32<<<dim3(F1 / 128, rowsBlocks), 256>>>(x, W1, p_h1, NN, 128, F1);
    attn_scores<64><<<nodeWarpBlocks, TB>>>(p_h1, as1, ad1, p_es, p_ed);
    gat_agg1<<<NN, 128>>>(p_h1, p_es, p_ed, b1, p_hr);

    // ---- layer 2 ----
    gemm_tf32<<<dim3(F2 / 128, rowsBlocks), 256>>>(p_hr, W2, p_h2, NN, 256, F2);
    attn_scores<128><<<nodeWarpBlocks, TB>>>(p_h2, as2, ad2, p_es, p_ed);
    gat_agg2<<<NN, 128>>>(p_h2, p_es, p_ed, b2, gamma, beta, out);
}

// round 7
// speedup vs baseline: 2.2621x; 1.2023x over previous
#include <cuda_runtime.h>
#include <math.h>

#define NN   50000
#define E0   800000
#define ETOT 850000
#define F1   256          // heads*HID  (layer-1 concat width)
#define F2   512          // heads*OUT  (layer-2 pre-mean width)
#define NT   49           // scan tiles of 1024

// ---------------- scratch (device globals; no allocations) ----------------
__device__ float g_h1[(size_t)NN * F1];    // layer1 pre-attn features
__device__ float g_hr[(size_t)NN * F1];    // layer1 post-attn relu output (GEMM2 input)
__device__ float g_h2[(size_t)NN * F2];    // layer2 pre-attn features
__device__ float g_es[NN * 4];             // e_src per node/head
__device__ float g_ed[NN * 4];             // e_dst per node/head
__device__ int   g_deg[NN];                // in-degree histogram
__device__ int   g_rowptr[NN + 1];         // CSR row offsets (by dst)
__device__ int   g_pos[NN];                // scatter cursors
__device__ int   g_srcs[ETOT];             // CSR column (src) indices
__device__ int   g_part[64];               // scan tile totals
__device__ int   g_partoff[64];            // scan tile exclusive offsets
__device__ int   g_is64;                   // 1 if edge_index is int64

// ---------------- dtype helpers ----------------
__device__ __forceinline__ void edge_nodes(const void* __restrict__ ei, int e,
                                           int& src, int& dst) {
    if (e >= E0) { src = dst = e - E0; return; }
    if (g_is64) {
        const long long* p = (const long long*)ei;
        src = (int)p[e];
        dst = (int)p[E0 + e];
    } else {
        const int* p = (const int*)ei;
        src = p[e];
        dst = p[E0 + e];
    }
}

// int64 little-endian node ids < 2^31 -> odd 32-bit words all zero.
__global__ void detect_idx_kernel(const int* __restrict__ ei32) {
    if (threadIdx.x == 0) {
        int all0 = 1;
        for (int i = 1; i < 256; i += 2) all0 &= (ei32[i] == 0);
        g_is64 = all0;
    }
}

// ---------------- CSR build ----------------
__global__ void zero_deg() {
    int i = blockIdx.x * blockDim.x + threadIdx.x;
    if (i < NN) g_deg[i] = 0;
}

__global__ void hist_kernel(const void* __restrict__ ei) {
    int e = blockIdx.x * blockDim.x + threadIdx.x;
    if (e >= ETOT) return;
    int src, dst;
    edge_nodes(ei, e, src, dst);
    atomicAdd(&g_deg[dst], 1);
}

// ---- parallel scan: (1) per-tile exclusive scan, (2) scan tile totals, (3) add offsets
__global__ void scan_tiles() {
    __shared__ int warpsum[32];
    int tid = threadIdx.x;
    int i = blockIdx.x * 1024 + tid;
    int lane = tid & 31, wid = tid >> 5;
    int v = (i < NN) ? g_deg[i] : 0;
    int s = v;
#pragma unroll
    for (int off = 1; off < 32; off <<= 1) {
        int t = __shfl_up_sync(0xffffffffu, s, off);
        if (lane >= off) s += t;
    }
    if (lane == 31) warpsum[wid] = s;
    __syncthreads();
    if (wid == 0) {
        int ws = warpsum[lane];
#pragma unroll
        for (int off = 1; off < 32; off <<= 1) {
            int t = __shfl_up_sync(0xffffffffu, ws, off);
            if (lane >= off) ws += t;
        }
        warpsum[lane] = ws;
    }
    __syncthreads();
    int excl = s - v + (wid > 0 ? warpsum[wid - 1] : 0);
    if (i < NN) g_rowptr[i] = excl;          // tile-local exclusive scan
    if (tid == 0) g_part[blockIdx.x] = warpsum[31];
}

__global__ void scan_parts() {  // 64 threads, Hillis-Steele in smem
    __shared__ int sp[64];
    int tid = threadIdx.x;
    int v = (tid < NT) ? g_part[tid] : 0;
    sp[tid] = v;
    __syncthreads();
#pragma unroll
    for (int off = 1; off < 64; off <<= 1) {
        int t = sp[tid];
        int add = (tid >= off) ? sp[tid - off] : 0;
        __syncthreads();
        sp[tid] = t + add;
        __syncthreads();
    }
    g_partoff[tid] = sp[tid] - v;            // exclusive
}

__global__ void add_offsets() {
    int i = blockIdx.x * 1024 + threadIdx.x;
    if (i < NN) {
        int r = g_rowptr[i] + g_partoff[blockIdx.x];
        g_rowptr[i] = r;
        g_pos[i]    = r;
    }
    if (i == 0) g_rowptr[NN] = ETOT;
}

__global__ void scatter_kernel(const void* __restrict__ ei) {
    int e = blockIdx.x * blockDim.x + threadIdx.x;
    if (e >= ETOT) return;
    int src, dst;
    edge_nodes(ei, e, src, dst);
    int p = atomicAdd(&g_pos[dst], 1);
    g_srcs[p] = src;
}

// ---------------- tf32 tensor-core GEMM: C[n,J] = A[n,K] @ B[K,J] ----------------
// block tile 64(M) x 128(N), K-step 32, 256 threads = 8 warps (2m x 4n), warp 32x32.
__device__ __forceinline__ unsigned f2tf32(float f) {
    unsigned r;
    asm("cvt.rna.tf32.f32 %0, %1;" : "=r"(r) : "f"(f));
    return r;
}
__device__ __forceinline__ void mma_tf32(float* d, const unsigned* a, const unsigned* b) {
    asm volatile(
        "mma.sync.aligned.m16n8k8.row.col.f32.tf32.tf32.f32 "
        "{%0,%1,%2,%3}, {%4,%5,%6,%7}, {%8,%9}, {%0,%1,%2,%3};"
        : "+f"(d[0]), "+f"(d[1]), "+f"(d[2]), "+f"(d[3])
        : "r"(a[0]), "r"(a[1]), "r"(a[2]), "r"(a[3]), "r"(b[0]), "r"(b[1]));
}

__global__ __launch_bounds__(256) void gemm_tf32(const float* __restrict__ A,
                                                 const float* __restrict__ B,
                                                 float* __restrict__ C,
                                                 int n, int K, int J) {
    __shared__ unsigned As[64][36];    // read bank = (4*lr+lc)%32, all 32 distinct
    __shared__ unsigned Bs[32][136];   // 128-wide tile + pad 8; read bank = (8*lc+lr)%32, distinct
    int tid  = threadIdx.x;
    int warp = tid >> 5, lane = tid & 31;
    int wm = (warp & 1) * 32;
    int wn = (warp >> 1) * 32;
    int row0 = blockIdx.y * 64;
    int col0 = blockIdx.x * 128;
    int lr = lane >> 2, lc = lane & 3;

    float acc[2][4][4];
#pragma unroll
    for (int i = 0; i < 2; i++)
#pragma unroll
        for (int j = 0; j < 4; j++)
#pragma unroll
            for (int q = 0; q < 4; q++) acc[i][j][q] = 0.f;

    for (int k0 = 0; k0 < K; k0 += 32) {
        {   // A tile 64x32: thread loads 8 floats (2 float4)
            int ar = tid >> 2;
            int ac = (tid & 3) * 8;
            int grow = row0 + ar;
            float4 v0 = make_float4(0.f, 0.f, 0.f, 0.f), v1 = v0;
            if (grow < n) {
                const float* ap = A + (size_t)grow * K + k0 + ac;
                v0 = *reinterpret_cast<const float4*>(ap);
                v1 = *reinterpret_cast<const float4*>(ap + 4);
            }
            As[ar][ac + 0] = f2tf32(v0.x); As[ar][ac + 1] = f2tf32(v0.y);
            As[ar][ac + 2] = f2tf32(v0.z); As[ar][ac + 3] = f2tf32(v0.w);
            As[ar][ac + 4] = f2tf32(v1.x); As[ar][ac + 5] = f2tf32(v1.y);
            As[ar][ac + 6] = f2tf32(v1.z); As[ar][ac + 7] = f2tf32(v1.w);
        }
        {   // B tile 32x128: thread loads 16 floats (4 float4)
            int br = tid >> 3;
            int bc = (tid & 7) * 16;
            const float* bp = B + (size_t)(k0 + br) * J + col0 + bc;
#pragma unroll
            for (int q = 0; q < 4; q++) {
                float4 v = *reinterpret_cast<const float4*>(bp + q * 4);
                Bs[br][bc + q * 4 + 0] = f2tf32(v.x);
                Bs[br][bc + q * 4 + 1] = f2tf32(v.y);
                Bs[br][bc + q * 4 + 2] = f2tf32(v.z);
                Bs[br][bc + q * 4 + 3] = f2tf32(v.w);
            }
        }
        __syncthreads();
#pragma unroll
        for (int kk = 0; kk < 32; kk += 8) {
            unsigned a[2][4], b[4][2];
#pragma unroll
            for (int mf = 0; mf < 2; mf++) {
                int r = wm + mf * 16 + lr;
                a[mf][0] = As[r][kk + lc];
                a[mf][1] = As[r + 8][kk + lc];
                a[mf][2] = As[r][kk + lc + 4];
                a[mf][3] = As[r + 8][kk + lc + 4];
            }
#pragma unroll
            for (int nf = 0; nf < 4; nf++) {
                int c = wn + nf * 8 + lr;
                b[nf][0] = Bs[kk + lc][c];
                b[nf][1] = Bs[kk + lc + 4][c];
            }
#pragma unroll
            for (int mf = 0; mf < 2; mf++)
#pragma unroll
                for (int nf = 0; nf < 4; nf++)
                    mma_tf32(acc[mf][nf], a[mf], b[nf]);
        }
        __syncthreads();
    }
    // store: c0 (r, c), c1 (r, c+1), c2 (r+8, c), c3 (r+8, c+1)
#pragma unroll
    for (int mf = 0; mf < 2; mf++) {
#pragma unroll
        for (int nf = 0; nf < 4; nf++) {
            int r = row0 + wm + mf * 16 + lr;
            int c = col0 + wn + nf * 8 + 2 * lc;
            if (r < n) {
                C[(size_t)r * J + c]     = acc[mf][nf][0];
                C[(size_t)r * J + c + 1] = acc[mf][nf][1];
            }
            if (r + 8 < n) {
                C[(size_t)(r + 8) * J + c]     = acc[mf][nf][2];
                C[(size_t)(r + 8) * J + c + 1] = acc[mf][nf][3];
            }
        }
    }
}

// ---------------- per-node attention scores: es/ed[n,h] = h[n,h,:]·a ----------------
template <int C>  // per-head channels (64 or 128)
__global__ void attn_scores(const float* __restrict__ h, const float* __restrict__ a_src,
                            const float* __restrict__ a_dst, float* __restrict__ es,
                            float* __restrict__ ed) {
    int warp = (blockIdx.x * blockDim.x + threadIdx.x) >> 5;
    int lane = threadIdx.x & 31;
    if (warp >= NN) return;
    const float4* hr  = reinterpret_cast<const float4*>(h + (size_t)warp * 4 * C);
    const float4* as4 = reinterpret_cast<const float4*>(a_src);
    const float4* ad4 = reinterpret_cast<const float4*>(a_dst);
    constexpr int Q = C / 32;
    float ss = 0.f, sd = 0.f;
#pragma unroll
    for (int q = 0; q < Q; q++) {
        int idx = lane * Q + q;  // lanes grouped by head (head = lane>>3)
        float4 hv = hr[idx];
        float4 av = as4[idx];
        float4 dv = ad4[idx];
        ss += hv.x * av.x + hv.y * av.y + hv.z * av.z + hv.w * av.w;
        sd += hv.x * dv.x + hv.y * dv.y + hv.z * dv.z + hv.w * dv.w;
    }
#pragma unroll
    for (int off = 4; off >= 1; off >>= 1) {
        ss += __shfl_down_sync(0xffffffffu, ss, off);
        sd += __shfl_down_sync(0xffffffffu, sd, off);
    }
    if ((lane & 7) == 0) {
        int head = lane >> 3;
        es[warp * 4 + head] = ss;
        ed[warp * 4 + head] = sd;
    }
}

// ---------------- fused per-node GAT aggregation (no max pass; scores bounded) -------
__device__ __forceinline__ float4 expleaky4(float4 a, float4 b) {
    float4 v;
    v.x = a.x + b.x; v.x = v.x > 0.f ? v.x : 0.2f * v.x; v.x = __expf(v.x);
    v.y = a.y + b.y; v.y = v.y > 0.f ? v.y : 0.2f * v.y; v.y = __expf(v.y);
    v.z = a.z + b.z; v.z = v.z > 0.f ? v.z : 0.2f * v.z; v.z = __expf(v.z);
    v.w = a.w + b.w; v.w = v.w > 0.f ? v.w : 0.2f * v.w; v.w = __expf(v.w);
    return v;
}

#define CHUNK 64

// Layer 1: softmax weights + accumulate + bias + relu.  128 threads/block, VEC=2.
__global__ __launch_bounds__(128) void gat_agg1(
    const float* __restrict__ h, const float* __restrict__ es, const float* __restrict__ ed,
    const float* __restrict__ bias, float* __restrict__ out) {
    int n = blockIdx.x;
    int tid = threadIdx.x;
    int lane = tid & 31, wid = tid >> 5;  // wid == head for owned channels
    int r0 = g_rowptr[n], r1 = g_rowptr[n + 1];
    int deg = r1 - r0;
    float4 edv = *reinterpret_cast<const float4*>(ed + n * 4);

    __shared__ float4 s_red[4];
    __shared__ int    s_src[CHUNK];
    __shared__ float4 s_w[CHUNK];

    float a0 = 0.f, a1 = 0.f;       // channels tid*2, tid*2+1 (head = wid)
    float4 dpart = make_float4(0.f, 0.f, 0.f, 0.f);
    for (int base = 0; base < deg; base += CHUNK) {
        int cn = deg - base; if (cn > CHUNK) cn = CHUNK;
        if (tid < cn) {
            int s = g_srcs[r0 + base + tid];
            float4 w = expleaky4(*reinterpret_cast<const float4*>(es + s * 4), edv);
            s_src[tid] = s;
            s_w[tid] = w;
            dpart.x += w.x; dpart.y += w.y; dpart.z += w.z; dpart.w += w.w;
        }
        __syncthreads();
        const float* wf = reinterpret_cast<const float*>(s_w);
        for (int j = 0; j < cn; j++) {
            int s = s_src[j];
            float w = wf[j * 4 + wid];
            float2 hv = *reinterpret_cast<const float2*>(h + (size_t)s * F1 + tid * 2);
            a0 += w * hv.x;
            a1 += w * hv.y;
        }
        __syncthreads();
    }
    // reduce denom
#pragma unroll
    for (int off = 16; off >= 1; off >>= 1) {
        dpart.x += __shfl_xor_sync(0xffffffffu, dpart.x, off);
        dpart.y += __shfl_xor_sync(0xffffffffu, dpart.y, off);
        dpart.z += __shfl_xor_sync(0xffffffffu, dpart.z, off);
        dpart.w += __shfl_xor_sync(0xffffffffu, dpart.w, off);
    }
    if (lane == 0) s_red[wid] = dpart;
    __syncthreads();
    float4 dt = s_red[0];
    dt.x += s_red[1].x + s_red[2].x + s_red[3].x;
    dt.y += s_red[1].y + s_red[2].y + s_red[3].y;
    dt.z += s_red[1].z + s_red[2].z + s_red[3].z;
    dt.w += s_red[1].w + s_red[2].w + s_red[3].w;
    float den = ((const float*)&dt)[wid] + 1e-16f;
    float inv = 1.f / den;
    int c = tid * 2;
    float o0 = a0 * inv + bias[c];
    float o1 = a1 * inv + bias[c + 1];
    o0 = o0 > 0.f ? o0 : 0.f;
    o1 = o1 > 0.f ? o1 : 0.f;
    *reinterpret_cast<float2*>(out + (size_t)n * F1 + c) = make_float2(o0, o1);
}

// Layer 2: softmax weights + accumulate + head-mean + bias + LayerNorm. VEC=4.
__global__ __launch_bounds__(128) void gat_agg2(
    const float* __restrict__ h, const float* __restrict__ es, const float* __restrict__ ed,
    const float* __restrict__ bias, const float* __restrict__ gamma,
    const float* __restrict__ beta, float* __restrict__ out) {
    int n = blockIdx.x;
    int tid = threadIdx.x;
    int lane = tid & 31, wid = tid >> 5;  // head = wid for owned channels
    int r0 = g_rowptr[n], r1 = g_rowptr[n + 1];
    int deg = r1 - r0;
    float4 edv = *reinterpret_cast<const float4*>(ed + n * 4);

    __shared__ float4 s_red[4];
    __shared__ int    s_src[CHUNK];
    __shared__ float4 s_w[CHUNK];
    __shared__ float  s_y[F2];
    __shared__ float  s_ln[4];

    float a0 = 0.f, a1 = 0.f, a2 = 0.f, a3 = 0.f;  // channels 4*tid..4*tid+3
    float4 dpart = make_float4(0.f, 0.f, 0.f, 0.f);
    for (int base = 0; base < deg; base += CHUNK) {
        int cn = deg - base; if (cn > CHUNK) cn = CHUNK;
        if (tid < cn) {
            int s = g_srcs[r0 + base + tid];
            float4 w = expleaky4(*reinterpret_cast<const float4*>(es + s * 4), edv);
            s_src[tid] = s;
            s_w[tid] = w;
            dpart.x += w.x; dpart.y += w.y; dpart.z += w.z; dpart.w += w.w;
        }
        __syncthreads();
        const float* wf = reinterpret_cast<const float*>(s_w);
        for (int j = 0; j < cn; j++) {
            int s = s_src[j];
            float w = wf[j * 4 + wid];
            float4 hv = *reinterpret_cast<const float4*>(h + (size_t)s * F2 + tid * 4);
            a0 += w * hv.x;
            a1 += w * hv.y;
            a2 += w * hv.z;
            a3 += w * hv.w;
        }
        __syncthreads();
    }
#pragma unroll
    for (int off = 16; off >= 1; off >>= 1) {
        dpart.x += __shfl_xor_sync(0xffffffffu, dpart.x, off);
        dpart.y += __shfl_xor_sync(0xffffffffu, dpart.y, off);
        dpart.z += __shfl_xor_sync(0xffffffffu, dpart.z, off);
        dpart.w += __shfl_xor_sync(0xffffffffu, dpart.w, off);
    }
    if (lane == 0) s_red[wid] = dpart;
    __syncthreads();
    float4 dt = s_red[0];
    dt.x += s_red[1].x + s_red[2].x + s_red[3].x;
    dt.y += s_red[1].y + s_red[2].y + s_red[3].y;
    dt.z += s_red[1].z + s_red[2].z + s_red[3].z;
    dt.w += s_red[1].w + s_red[2].w + s_red[3].w;
    float inv = 1.f / (((const float*)&dt)[wid] + 1e-16f);
    int l = tid * 4;
    s_y[l + 0] = a0 * inv;
    s_y[l + 1] = a1 * inv;
    s_y[l + 2] = a2 * inv;
    s_y[l + 3] = a3 * inv;
    __syncthreads();

    // head-mean + bias, then LayerNorm over 128 channels
    int c = tid;
    float y = 0.25f * (s_y[c] + s_y[128 + c] + s_y[256 + c] + s_y[384 + c]) + bias[c];
    float t = y;
#pragma unroll
    for (int off = 16; off >= 1; off >>= 1) t += __shfl_xor_sync(0xffffffffu, t, off);
    if (lane == 0) s_ln[wid] = t;
    __syncthreads();
    float mu = (s_ln[0] + s_ln[1] + s_ln[2] + s_ln[3]) * (1.f / 128.f);
    float dv = y - mu;
    t = dv * dv;
#pragma unroll
    for (int off = 16; off >= 1; off >>= 1) t += __shfl_xor_sync(0xffffffffu, t, off);
    __syncthreads();
    if (lane == 0) s_ln[wid] = t;
    __syncthreads();
    float var = (s_ln[0] + s_ln[1] + s_ln[2] + s_ln[3]) * (1.f / 128.f);
    out[(size_t)n * 128 + c] = dv * rsqrtf(var + 1e-5f) * gamma[c] + beta[c];
}

// ---------------- launch ----------------
extern "C" void kernel_launch(void* const* d_in, const int* in_sizes, int n_in,
                              void* d_out, int out_size) {
    const float* x     = (const float*)d_in[0];
    const void*  ei    = d_in[1];               // int32 or int64, detected on device
    const float* W1    = (const float*)d_in[2];
    const float* as1   = (const float*)d_in[3];
    const float* ad1   = (const float*)d_in[4];
    const float* b1    = (const float*)d_in[5];
    const float* W2    = (const float*)d_in[6];
    const float* as2   = (const float*)d_in[7];
    const float* ad2   = (const float*)d_in[8];
    const float* b2    = (const float*)d_in[9];
    const float* gamma = (const float*)d_in[10];
    const float* beta  = (const float*)d_in[11];
    float*       out   = (float*)d_out;

    float *p_h1, *p_hr, *p_h2, *p_es, *p_ed;
    cudaGetSymbolAddress((void**)&p_h1, g_h1);
    cudaGetSymbolAddress((void**)&p_hr, g_hr);
    cudaGetSymbolAddress((void**)&p_h2, g_h2);
    cudaGetSymbolAddress((void**)&p_es, g_es);
    cudaGetSymbolAddress((void**)&p_ed, g_ed);

    const int TB = 256;
    int rowsBlocks = (NN + 63) / 64;            // 782
    int nodeWarpBlocks = (NN + 7) / 8;          // 6250
    int edgeBlocks = (ETOT + TB - 1) / TB;      // 3321

    // ---- CSR build (shared by both layers) ----
    detect_idx_kernel<<<1, 32>>>((const int*)ei);
    zero_deg<<<(NN + TB - 1) / TB, TB>>>();
    hist_kernel<<<edgeBlocks, TB>>>(ei);
    scan_tiles<<<NT, 1024>>>();
    scan_parts<<<1, 64>>>();
    add_offsets<<<NT, 1024>>>();
    scatter_kernel<<<edgeBlocks, TB>>>(ei);

    // ---- layer 1 ----
    gemm_tf32<<<dim3(F1 / 128, rowsBlocks), 256>>>(x, W1, p_h1, NN, 128, F1);
    attn_scores<64><<<nodeWarpBlocks, TB>>>(p_h1, as1, ad1, p_es, p_ed);
    gat_agg1<<<NN, 128>>>(p_h1, p_es, p_ed, b1, p_hr);

    // ---- layer 2 ----
    gemm_tf32<<<dim3(F2 / 128, rowsBlocks), 256>>>(p_hr, W2, p_h2, NN, 256, F2);
    attn_scores<128><<<nodeWarpBlocks, TB>>>(p_h2, as2, ad2, p_es, p_ed);
    gat_agg2<<<NN, 128>>>(p_h2, p_es, p_ed, b2, gamma, beta, out);
}